// round 3
// baseline (speedup 1.0000x reference)
#include <cuda_runtime.h>
#include <cstdint>

// scatter_mean: out[s, :] = mean over rows r with index[r]==s of x[r, :]
// x: [N, 64] f32, index: [N] int32 (JAX x64-disabled downcast), out: [S, 64] f32

#define DVEC 16          // 64 floats = 16 float4 per row
#define MAX_SEG 100000

__device__ float g_counts[MAX_SEG];

__global__ void init_kernel(float* __restrict__ out, int total_out, int S) {
    int i = blockIdx.x * blockDim.x + threadIdx.x;
    int stride = gridDim.x * blockDim.x;
    for (; i < total_out + S; i += stride) {
        if (i < total_out) out[i] = 0.0f;
        else               g_counts[i - total_out] = 0.0f;
    }
}

__global__ void scatter_kernel(const float4* __restrict__ x,
                               const int* __restrict__ idx,
                               float* __restrict__ out,
                               int nrows) {
    long long t = (long long)blockIdx.x * blockDim.x + threadIdx.x;
    long long total = (long long)nrows * DVEC;
    if (t >= total) return;

    int row = (int)(t >> 4);
    int q   = (int)(t & 15);

    int s = idx[row];                // 16 neighboring threads share this -> L1 hit
    float4 v = x[t];                 // fully coalesced streaming read

    float* dst = out + (long long)s * 64 + q * 4;
    asm volatile("red.global.add.v4.f32 [%0], {%1, %2, %3, %4};"
                 :: "l"(dst), "f"(v.x), "f"(v.y), "f"(v.z), "f"(v.w)
                 : "memory");

    if (q == 0) atomicAdd(&g_counts[s], 1.0f);
}

__global__ void divide_kernel(float* __restrict__ out, int total_out) {
    int i = blockIdx.x * blockDim.x + threadIdx.x;
    if (i >= total_out) return;
    int s = i >> 6;                  // 64 floats per segment
    float c = g_counts[s];
    out[i] = out[i] / fmaxf(c, 1.0f);
}

extern "C" void kernel_launch(void* const* d_in, const int* in_sizes, int n_in,
                              void* d_out, int out_size) {
    const float4* x   = (const float4*)d_in[0];
    const int*    idx = (const int*)d_in[1];
    float*        out = (float*)d_out;

    int nrows = in_sizes[1];              // N = 4194304
    int S     = out_size / 64;            // 100000
    int total_out = out_size;             // S * 64

    {
        int threads = 256;
        int work = total_out + S;
        int blocks = (work + threads - 1) / threads;
        if (blocks > 4096) blocks = 4096;
        init_kernel<<<blocks, threads>>>(out, total_out, S);
    }
    {
        long long total = (long long)nrows * DVEC;   // 67,108,864 threads
        int threads = 256;
        long long blocks = (total + threads - 1) / threads;
        scatter_kernel<<<(unsigned int)blocks, threads>>>(x, idx, out, nrows);
    }
    {
        int threads = 256;
        int blocks = (total_out + threads - 1) / threads;
        divide_kernel<<<blocks, threads>>>(out, total_out);
    }
}